// round 8
// baseline (speedup 1.0000x reference)
#include <cuda_runtime.h>
#include <cuda_fp16.h>
#include <mma.h>
#include <cstdint>

using namespace nvcuda;

#define BB 256
#define TT 512
#define II 256
#define HH 512
#define G4 2048
#define K0 768
#define K1 1024
#define KC 128
#define NBLK 128
#define NTHR 512
#define LDA 136            // halves
#define LDB 136
#define LDC 136            // floats
#define A_BYTES (64 * LDA * 2)                    // 17408
#define B_BYTES (KC * LDB * 2)                    // 34816
#define STAGE_BYTES (A_BYTES + B_BYTES)           // 52224
#define SMEM_DYN (4 * STAGE_BYTES)                // 208896

// ---------------- device global scratch ----------------
__device__ __half g_Xh[(size_t)TT * BB * II];            // [T][B][I]
__device__ __half g_W0[(size_t)K0 * G4];                 // rows [W_ih0; W_hh0]
__device__ __half g_W1[(size_t)K1 * G4];                 // rows [W_ih1; W_hh1]  (h0 part FIRST)
__device__ float  g_bias0[G4];
__device__ float  g_bias1[G4];
__device__ __half g_h0[(size_t)(TT + 1) * BB * HH];      // slot t+1 = output of step t
__device__ __half g_h1[(size_t)(TT + 1) * BB * HH];
__device__ int    g_flag0[(TT + 1) * 4];
__device__ int    g_flag1[(TT + 1) * 4];
__device__ unsigned long long g_count = 0;
__device__ volatile unsigned long long g_epoch = 0;

__device__ __forceinline__ void grid_barrier() {
    __syncthreads();
    if (threadIdx.x == 0) {
        __threadfence();
        unsigned long long e = g_epoch;
        if (atomicAdd(&g_count, 1ULL) == (unsigned long long)(NBLK - 1)) {
            g_count = 0;
            __threadfence();
            g_epoch = e + 1;
        } else {
            while (g_epoch == e) { __nanosleep(64); }
        }
    }
    __syncthreads();
}

__device__ __forceinline__ float sig_(float x) {
    return __fdividef(1.0f, 1.0f + __expf(-x));
}
__device__ __forceinline__ float tanh_(float x) {
    return __fmaf_rn(2.0f, sig_(2.0f * x), -1.0f);
}

__device__ __forceinline__ void cp_async16(void* smem, const void* g) {
    unsigned s = (unsigned)__cvta_generic_to_shared(smem);
    asm volatile("cp.async.cg.shared.global [%0], [%1], 16;" :: "r"(s), "l"(g));
}
__device__ __forceinline__ void cp_commit() { asm volatile("cp.async.commit_group;"); }
template <int N> __device__ __forceinline__ void cp_wait() {
    asm volatile("cp.async.wait_group %0;" :: "n"(N));
}
__device__ __forceinline__ void group_bar(int g) {
    asm volatile("bar.sync %0, 256;" :: "r"(g + 1) : "memory");
}

__device__ __forceinline__ void poll_flag(const int* f) {
    int v = __ldcg(f);
    if (v < 16) {
        do { __nanosleep(32); v = __ldcg(f); } while (v < 16);
    }
    __threadfence();   // acquire
}
__device__ __forceinline__ void release_flag(int* f) {
    __threadfence();
    atomicAdd(f, 1);
}

// A: 64 rows x 128 halves
__device__ __forceinline__ void loadA(char* stage, int gt,
                                      const __half* __restrict__ Abase, int lda) {
    __half* sA = (__half*)stage;
#pragma unroll
    for (int i = 0; i < 4; ++i) {
        int idx = gt + i * 256;
        int r = idx >> 4, u = (idx & 15) << 3;
        cp_async16(sA + r * LDA + u, Abase + (size_t)r * lda + u);
    }
}
// B: 128 k-rows x 128 cols
__device__ __forceinline__ void loadB(char* stage, int gt,
                                      const __half* __restrict__ Bbase) {
    __half* sB = (__half*)(stage + A_BYTES);
#pragma unroll
    for (int i = 0; i < 8; ++i) {
        int idx = gt + i * 256;
        int r = idx >> 4, u = (idx & 15) << 3;
        cp_async16(sB + r * LDB + u, Bbase + (size_t)r * G4 + u);
    }
}

__global__ void __launch_bounds__(NTHR, 1)
lstm_kernel(const float* __restrict__ X,
            const float* __restrict__ Wih0, const float* __restrict__ Whh0,
            const float* __restrict__ bih0, const float* __restrict__ bhh0,
            const float* __restrict__ Wih1, const float* __restrict__ Whh1,
            const float* __restrict__ bih1, const float* __restrict__ bhh1,
            const float* __restrict__ Wlin, const float* __restrict__ blin,
            float* __restrict__ out)
{
    extern __shared__ __align__(128) char smem[];

    const int tid = threadIdx.x;
    const int gtid = blockIdx.x * NTHR + tid;
    const int gstride = NBLK * NTHR;

    // ---------------- prologue ----------------
    for (int i = gtid; i < BB * TT * II; i += gstride) {
        int b = i >> 17;
        int rem = i & 131071;
        int t = rem >> 8;
        int ii = rem & 255;
        g_Xh[((size_t)t * BB + b) * II + ii] = __float2half(X[i]);
    }
    for (int i = gtid; i < G4 * II; i += gstride) {          // W_ih0 -> rows 0..255
        int r = i >> 8, k = i & 255;
        int n = ((r & 511) << 2) | (r >> 9);
        g_W0[(size_t)k * G4 + n] = __float2half(Wih0[i]);
    }
    for (int i = gtid; i < G4 * HH; i += gstride) {          // W_hh0 -> rows 256..767
        int r = i >> 9, k = i & 511;
        int n = ((r & 511) << 2) | (r >> 9);
        g_W0[(size_t)(II + k) * G4 + n] = __float2half(Whh0[i]);
    }
    for (int i = gtid; i < G4 * HH; i += gstride) {          // W_ih1 -> rows 0..511 (h0 part first!)
        int r = i >> 9, k = i & 511;
        int n = ((r & 511) << 2) | (r >> 9);
        g_W1[(size_t)k * G4 + n] = __float2half(Wih1[i]);
    }
    for (int i = gtid; i < G4 * HH; i += gstride) {          // W_hh1 -> rows 512..1023
        int r = i >> 9, k = i & 511;
        int n = ((r & 511) << 2) | (r >> 9);
        g_W1[(size_t)(HH + k) * G4 + n] = __float2half(Whh1[i]);
    }
    for (int i = gtid; i < G4; i += gstride) {
        int n = ((i & 511) << 2) | (i >> 9);
        g_bias0[n] = bih0[i] + bhh0[i];
        g_bias1[n] = bih1[i] + bhh1[i];
    }
    for (int i = gtid; i < BB * HH; i += gstride) {
        __half z = __float2half(0.0f);
        g_h0[i] = z; g_h1[i] = z;
    }
    for (int i = gtid; i < (TT + 1) * 4; i += gstride) {
        int v = (i < 4) ? 16 : 0;
        g_flag0[i] = v; g_flag1[i] = v;
    }
    grid_barrier();

    // ---------------- per-block tile ----------------
    const int blk = blockIdx.x;
    const bool is_l1 = (blk >= 64);
    const int tile = is_l1 ? (blk - 64) : blk;
    const int slab = tile >> 4;
    const int m0 = slab * 64;
    const int n0 = (tile & 15) * 128;
    const int nch2 = is_l1 ? 4 : 3;                  // chunks per group
    const __half* W = is_l1 ? g_W1 : g_W0;
    const float* bias = is_l1 ? g_bias1 : g_bias0;
    __half* hist_out = is_l1 ? g_h1 : g_h0;
    int* flag_out = is_l1 ? g_flag1 : g_flag0;

    const int warp = tid >> 5;
    const int g = warp >> 3;
    const int gwarp = warp & 7;
    const int gt = tid & 255;
    const int wm = gwarp >> 2;
    const int wn = gwarp & 3;
    char* gst[2] = { smem + (g * 2) * STAGE_BYTES,          // stage 0
                     smem + (g * 2 + 1) * STAGE_BYTES };    // stage 1 (sC aliases this)
    float* sC0 = (float*)(smem + 1 * STAGE_BYTES);
    float* sC1 = (float*)(smem + 3 * STAGE_BYTES);
    float* sCg = g ? sC1 : sC0;

    float c_reg[4];
#pragma unroll
    for (int j = 0; j < 4; ++j) c_reg[j] = 0.0f;

    // initial prefetch for t=0, chunk c=g -> stage 0
    if (!is_l1) {
        // x(0) chunk g: A + B, no flag needed
        loadA(gst[0], gt, g_Xh + (size_t)m0 * II + g * KC, II);
        loadB(gst[0], gt, W + (size_t)g * KC * G4 + n0);
        cp_commit();
    } else {
        // B only (weights); A (h0) loaded at loop top after poll
        loadB(gst[0], gt, W + (size_t)g * KC * G4 + n0);
        cp_commit();
    }

    for (int t = 0; t < TT; ++t) {
        const __half* h0s = g_h0 + (size_t)(is_l1 ? (t + 1) : t) * BB * HH;
        const __half* h1s = g_h1 + (size_t)t * BB * HH;
        const __half* xb = g_Xh + (size_t)t * BB * II;

        // chunk A source: l0: [x(2) | h0(t-1)(4)] ; l1: [h0(t)(4) | h1(t-1)(4)]
        auto Asrc = [&](int c, const __half*& s, int& ld) {
            if (!is_l1) {
                if (c < 2) { s = xb + (size_t)m0 * II + c * KC; ld = II; }
                else       { s = h0s + (size_t)m0 * HH + (c - 2) * KC; ld = HH; }
            } else {
                if (c < 4) { s = h0s + (size_t)m0 * HH + c * KC; ld = HH; }
                else       { s = h1s + (size_t)m0 * HH + (c - 4) * KC; ld = HH; }
            }
        };

        // l1: h0(t) flag, then load chunk-0 A (B already in flight from cross-step prefetch)
        if (is_l1) {
            poll_flag(&g_flag0[(t + 1) * 4 + slab]);
            const __half* s; int ld; Asrc(g, s, ld);
            loadA(gst[0], gt, s, ld);
            cp_commit();
        }

        wmma::fragment<wmma::accumulator, 16, 16, 16, float> cf[2][2];
#pragma unroll
        for (int i = 0; i < 2; ++i)
#pragma unroll
            for (int j = 0; j < 2; ++j)
                wmma::fill_fragment(cf[i][j], 0.0f);

        for (int l = 0; l < nch2; ++l) {
            const int c = 2 * l + g;
            cp_wait<0>();
            group_bar(g);
            if (l + 1 < nch2) {
                const int cn = c + 2;
                if (!is_l1 && l + 1 == 1) poll_flag(&g_flag0[t * 4 + slab]);   // h0(t-1)
                if (is_l1 && l + 1 == 2)  poll_flag(&g_flag1[t * 4 + slab]);   // h1(t-1)
                const __half* s; int ld; Asrc(cn, s, ld);
                char* st = gst[(l + 1) & 1];
                loadA(st, gt, s, ld);
                loadB(st, gt, W + (size_t)cn * KC * G4 + n0);
                cp_commit();
            }
            // compute chunk c from stage l&1
            __half* sA = (__half*)gst[l & 1];
            __half* sB = (__half*)(gst[l & 1] + A_BYTES);
#pragma unroll
            for (int ks = 0; ks < KC; ks += 16) {
                wmma::fragment<wmma::matrix_a, 16, 16, 16, __half, wmma::row_major> af[2];
                wmma::fragment<wmma::matrix_b, 16, 16, 16, __half, wmma::row_major> bf[2];
#pragma unroll
                for (int i = 0; i < 2; ++i)
                    wmma::load_matrix_sync(af[i], sA + (wm * 32 + i * 16) * LDA + ks, LDA);
#pragma unroll
                for (int j = 0; j < 2; ++j)
                    wmma::load_matrix_sync(bf[j], sB + ks * LDB + wn * 32 + j * 16, LDB);
#pragma unroll
                for (int i = 0; i < 2; ++i)
#pragma unroll
                    for (int j = 0; j < 2; ++j)
                        wmma::mma_sync(cf[i][j], af[i], bf[j], cf[i][j]);
            }
        }
        group_bar(g);        // all group warps finished all computes (stage 0 free)

        // cross-step prefetch into stage 0 (before epilogue)
        if (t + 1 < TT) {
            if (!is_l1) {
                loadA(gst[0], gt, g_Xh + (size_t)(t + 1) * BB * II + (size_t)m0 * II + g * KC, II);
                loadB(gst[0], gt, W + (size_t)g * KC * G4 + n0);
                cp_commit();
            } else {
                loadB(gst[0], gt, W + (size_t)g * KC * G4 + n0);
                cp_commit();
            }
        }

        // epilogue: accumulators -> sC (stage-1 alias), then fused LSTM cell
#pragma unroll
        for (int i = 0; i < 2; ++i)
#pragma unroll
            for (int j = 0; j < 2; ++j)
                wmma::store_matrix_sync(sCg + (wm * 32 + i * 16) * LDC + (wn * 32 + j * 16),
                                        cf[i][j], LDC, wmma::mem_row_major);
        __syncthreads();

        __half* hout = hist_out + (size_t)(t + 1) * BB * HH;
        {
            const int r = tid >> 3;              // 0..63
            const int jq = (tid & 7) * 4;        // unit quad base (0..31 step 4)
            const int b = m0 + r;
            unsigned short hs[4];
#pragma unroll
            for (int q = 0; q < 4; ++q) {
                int col = 4 * (jq + q);
                float4 g0 = *(float4*)(sC0 + r * LDC + col);
                float4 g1 = *(float4*)(sC1 + r * LDC + col);
                float4 bv = *(const float4*)(bias + n0 + col);
                float iv = sig_(g0.x + g1.x + bv.x);
                float fv = sig_(g0.y + g1.y + bv.y);
                float gg = tanh_(g0.z + g1.z + bv.z);
                float ov = sig_(g0.w + g1.w + bv.w);
                float cc = fv * c_reg[q] + iv * gg;
                c_reg[q] = cc;
                hs[q] = __half_as_ushort(__float2half(ov * tanh_(cc)));
            }
            uint2 hv;
            hv.x = (uint32_t)hs[0] | ((uint32_t)hs[1] << 16);
            hv.y = (uint32_t)hs[2] | ((uint32_t)hs[3] << 16);
            asm volatile("st.global.cg.v2.u32 [%0], {%1,%2};"
                         :: "l"(hout + (size_t)b * HH + (n0 >> 2) + jq),
                            "r"(hv.x), "r"(hv.y) : "memory");
        }
        __syncthreads();
        if (tid == 0) release_flag(&flag_out[(t + 1) * 4 + slab]);
    }

    // ---------------- head ----------------
    if (is_l1 && (tile & 15) == 0) {
        poll_flag(&g_flag1[TT * 4 + slab]);
        const __half* hfin = g_h1 + (size_t)TT * BB * HH;
        if (tid < 64) {
            int b = m0 + tid;
            float acc = blin[0];
            for (int k = 0; k < HH; k += 8) {
                uint4 v = __ldcg((const uint4*)(hfin + (size_t)b * HH + k));
                const __half* hv = (const __half*)&v;
#pragma unroll
                for (int u = 0; u < 8; ++u)
                    acc += __half2float(hv[u]) * Wlin[k + u];
            }
            out[b] = acc;
        }
    }
}

extern "C" void kernel_launch(void* const* d_in, const int* in_sizes, int n_in,
                              void* d_out, int out_size) {
    (void)in_sizes; (void)n_in; (void)out_size;
    cudaFuncSetAttribute(lstm_kernel,
                         cudaFuncAttributeMaxDynamicSharedMemorySize, SMEM_DYN);
    lstm_kernel<<<NBLK, NTHR, SMEM_DYN>>>(
        (const float*)d_in[0],
        (const float*)d_in[1], (const float*)d_in[2],
        (const float*)d_in[3], (const float*)d_in[4],
        (const float*)d_in[5], (const float*)d_in[6],
        (const float*)d_in[7], (const float*)d_in[8],
        (const float*)d_in[9], (const float*)d_in[10],
        (float*)d_out);
}